// round 2
// baseline (speedup 1.0000x reference)
#include <cuda_runtime.h>
#include <cuda_bf16.h>
#include <cstdint>

// Problem constants (fixed by reference setup_inputs)
#define Bb   8
#define Nn   1024
#define Hh   8
#define HDd  16
#define Dd   128          // H*HD = OUT_DIM = IN_DIM
#define ROWS (Bb*Nn)      // 8192
#define EPSc 1e-5f

// ---------------- scratch (static device allocations; no cudaMalloc) --------
__device__ float              g_Wt[Dd*Dd];                    // W reordered to [i][h*16+d]
__device__ float              g_Wh[ROWS*Dd];                  // [b*N+n][h*16+d]
__device__ float4             g_q[Bb*Hh*Nn];                  // {s_i, e^{s_i}, e^{0.2 s_i}, 0}
__device__ float4             g_k[Bb*Hh*Nn];                  // {s_j, e^{s_j}, e^{0.2 s_j}, 0}
__device__ unsigned long long g_maskbits[(size_t)ROWS*Nn/64]; // bit m of row (b,n)
__device__ float              g_hcat[ROWS*Dd];                // attention output (pre-LN)
__device__ float              g_x[ROWS*Dd];                   // post-LN1
__device__ float              g_y[ROWS*2*Dd];                 // FFN hidden
__device__ float              g_z[ROWS*Dd];                   // FFN out (incl. b2)

// ---------------- helpers ---------------------------------------------------
__device__ __forceinline__ unsigned long long pack2(float x) {
    unsigned long long r;
    asm("mov.b64 %0, {%1, %1};" : "=l"(r) : "f"(x));
    return r;
}
__device__ __forceinline__ void fma2(unsigned long long& acc, unsigned long long ab,
                                     unsigned long long c) {
    asm("fma.rn.f32x2 %0, %1, %2, %0;" : "+l"(acc) : "l"(ab), "l"(c));
}

// ---------------- 1. pack adjacency mask into bits --------------------------
__global__ __launch_bounds__(1024) void pack_mask_kernel(const int* __restrict__ adj) {
    int tid = blockIdx.x * blockDim.x + threadIdx.x;   // = (b*N+n)*N + m
    int v = adj[tid];
    unsigned bal = __ballot_sync(0xffffffffu, v != 0);
    if ((threadIdx.x & 31) == 0)
        ((unsigned*)g_maskbits)[tid >> 5] = bal;
}

// ---------------- 2. reorder W (H,IN,HD) -> Wt (IN, H*HD) -------------------
__global__ void transpose_w_kernel(const float* __restrict__ W) {
    int tid = blockIdx.x * blockDim.x + threadIdx.x;   // < 128*128
    int i = tid >> 7;
    int o = tid & 127;
    int h = o >> 4, d = o & 15;
    g_Wt[tid] = W[(h << 11) + (i << 4) + d];
}

// ---------------- generic tiled SGEMM: C = act(A@B + bias) ------------------
// A: M x K, B: K x N, C: M x N.  64x64 tile, 256 threads, 4x4 micro-tile.
__global__ __launch_bounds__(256) void sgemm_kernel(
        const float* __restrict__ A, const float* __restrict__ Bm,
        const float* __restrict__ bias, float* __restrict__ C,
        int M, int N, int K, int relu) {
    __shared__ float As[16][68];   // [k][row], padded
    __shared__ float Bs[16][64];   // [k][col]
    int t  = threadIdx.x;
    int tx = t & 15, ty = t >> 4;
    int row0 = blockIdx.y * 64, col0 = blockIdx.x * 64;

    float acc[4][4];
#pragma unroll
    for (int i = 0; i < 4; i++)
#pragma unroll
        for (int j = 0; j < 4; j++) acc[i][j] = 0.f;

    for (int k0 = 0; k0 < K; k0 += 16) {
        {
            int ar = t >> 2, ak = (t & 3) << 2;
            float4 v = *(const float4*)&A[(size_t)(row0 + ar) * K + k0 + ak];
            As[ak + 0][ar] = v.x; As[ak + 1][ar] = v.y;
            As[ak + 2][ar] = v.z; As[ak + 3][ar] = v.w;
            int bk = t >> 4, bc = (t & 15) << 2;
            *(float4*)&Bs[bk][bc] = *(const float4*)&Bm[(size_t)(k0 + bk) * N + col0 + bc];
        }
        __syncthreads();
#pragma unroll
        for (int k = 0; k < 16; k++) {
            float4 a4 = *(const float4*)&As[k][ty << 2];
            float4 b4 = *(const float4*)&Bs[k][tx << 2];
            float av[4] = {a4.x, a4.y, a4.z, a4.w};
            float bv[4] = {b4.x, b4.y, b4.z, b4.w};
#pragma unroll
            for (int i = 0; i < 4; i++)
#pragma unroll
                for (int j = 0; j < 4; j++) acc[i][j] += av[i] * bv[j];
        }
        __syncthreads();
    }

    float bv[4];
#pragma unroll
    for (int j = 0; j < 4; j++) bv[j] = bias ? bias[col0 + (tx << 2) + j] : 0.f;
#pragma unroll
    for (int i = 0; i < 4; i++) {
        float4 r;
        r.x = acc[i][0] + bv[0]; r.y = acc[i][1] + bv[1];
        r.z = acc[i][2] + bv[2]; r.w = acc[i][3] + bv[3];
        if (relu) {
            r.x = fmaxf(r.x, 0.f); r.y = fmaxf(r.y, 0.f);
            r.z = fmaxf(r.z, 0.f); r.w = fmaxf(r.w, 0.f);
        }
        *(float4*)&C[(size_t)(row0 + (ty << 2) + i) * N + col0 + (tx << 2)] = r;
    }
}

// ---------------- 3. attention scores + exp factor tables -------------------
__global__ __launch_bounds__(1024) void sE_kernel(const float* __restrict__ a) {
    int idx = blockIdx.x * blockDim.x + threadIdx.x;   // (b*H+h)*N + n
    int n = idx & 1023;
    int h = (idx >> 10) & 7;
    int b = idx >> 13;
    const float* wrow = &g_Wh[(size_t)((b << 10) | n) * Dd + (h << 4)];
    const float* ah   = a + h * 32;
    float si = 0.f, sj = 0.f;
#pragma unroll
    for (int d = 0; d < 16; d++) {
        float wv = wrow[d];
        si += wv * ah[d];
        sj += wv * ah[16 + d];
    }
    g_q[idx] = make_float4(si, __expf(si), __expf(0.2f * si), 0.f);
    g_k[idx] = make_float4(sj, __expf(sj), __expf(0.2f * sj), 0.f);
}

// ---------------- 4. fused masked-softmax attention -------------------------
// grid (N/128, H, B), 128 threads: one thread per query row n.
#define ATT_TM 64
__global__ __launch_bounds__(128) void att_kernel() {
    int b = blockIdx.z, h = blockIdx.y;
    int n = blockIdx.x * 128 + threadIdx.x;

    __shared__ float4 sk[ATT_TM];
    __shared__ float  swh[ATT_TM][16];

    int bhN = (b * Hh + h) * Nn;
    int bN  = b * Nn;
    float4 q = g_q[bhN + n];
    float s_i = q.x, E1 = q.y, E2 = q.z;

    unsigned long long acc[8];
#pragma unroll
    for (int j = 0; j < 8; j++) acc[j] = 0ULL;
    float sumw = 0.f;

    const unsigned long long* mrow = g_maskbits + (size_t)(bN + n) * (Nn / 64);

    for (int m0 = 0; m0 < Nn; m0 += ATT_TM) {
        __syncthreads();
        int t = threadIdx.x;
        if (t < ATT_TM) sk[t] = g_k[bhN + m0 + t];
#pragma unroll
        for (int j = 0; j < 2; j++) {
            int idx = t + j * 128;              // 0..255 float4 slots
            int mi = idx >> 2, q4 = idx & 3;
            ((float4*)swh[mi])[q4] =
                *(const float4*)&g_Wh[(size_t)(bN + m0 + mi) * Dd + (h << 4) + (q4 << 2)];
        }
        __syncthreads();

        unsigned long long bits = mrow[m0 >> 6];
#pragma unroll 8
        for (int mm = 0; mm < ATT_TM; mm++) {
            float4 k4 = sk[mm];
            float ts = s_i + k4.x;
            bool pos = (ts >= 0.f);
            float w = (pos ? E1 : E2) * (pos ? k4.y : k4.z);
            if (!((bits >> mm) & 1ULL)) w = 0.f;
            sumw += w;
            unsigned long long w2 = pack2(w);
            const unsigned long long* wrow = (const unsigned long long*)swh[mm];
#pragma unroll
            for (int j = 0; j < 8; j++) fma2(acc[j], w2, wrow[j]);
        }
    }

    float inv = (sumw > 0.f) ? __fdividef(1.f, sumw) : 0.f;
    float* dst = &g_hcat[(size_t)(bN + n) * Dd + (h << 4)];
#pragma unroll
    for (int j = 0; j < 8; j++) {
        float2 v = *(float2*)&acc[j];
        v.x *= inv; v.y *= inv;
        ((float2*)dst)[j] = v;
    }
}

// ---------------- 5. layernorm (optional residual) --------------------------
__global__ __launch_bounds__(128) void ln_kernel(
        const float* __restrict__ A, const float* __restrict__ R,
        const float* __restrict__ g, const float* __restrict__ bta,
        float* __restrict__ out) {
    int row = blockIdx.x;
    int c = threadIdx.x;
    size_t base = (size_t)row * Dd;
    float v = A[base + c];
    if (R) v += R[base + c];
    float s = v, s2 = v * v;
#pragma unroll
    for (int o = 16; o > 0; o >>= 1) {
        s  += __shfl_xor_sync(0xffffffffu, s,  o);
        s2 += __shfl_xor_sync(0xffffffffu, s2, o);
    }
    __shared__ float ws[4], ws2[4];
    int w = threadIdx.x >> 5;
    if ((threadIdx.x & 31) == 0) { ws[w] = s; ws2[w] = s2; }
    __syncthreads();
    s  = ws[0]  + ws[1]  + ws[2]  + ws[3];
    s2 = ws2[0] + ws2[1] + ws2[2] + ws2[3];
    float mu  = s * (1.f / Dd);
    float var = s2 * (1.f / Dd) - mu * mu;
    float r = rsqrtf(var + EPSc);
    out[base + c] = (v - mu) * r * g[c] + bta[c];
}

// ---------------- launch ----------------------------------------------------
extern "C" void kernel_launch(void* const* d_in, const int* in_sizes, int n_in,
                              void* d_out, int out_size) {
    const float* h    = (const float*)d_in[0];
    const int*   adj  = (const int*)d_in[1];
    const float* W    = (const float*)d_in[2];
    const float* a    = (const float*)d_in[3];
    const float* ln1g = (const float*)d_in[4];
    const float* ln1b = (const float*)d_in[5];
    const float* w1   = (const float*)d_in[6];
    const float* b1   = (const float*)d_in[7];
    const float* w2   = (const float*)d_in[8];
    const float* b2   = (const float*)d_in[9];
    const float* ln2g = (const float*)d_in[10];
    const float* ln2b = (const float*)d_in[11];
    float* out = (float*)d_out;

    float *Wt, *Wh, *hcat, *x, *y, *z;
    cudaGetSymbolAddress((void**)&Wt,   g_Wt);
    cudaGetSymbolAddress((void**)&Wh,   g_Wh);
    cudaGetSymbolAddress((void**)&hcat, g_hcat);
    cudaGetSymbolAddress((void**)&x,    g_x);
    cudaGetSymbolAddress((void**)&y,    g_y);
    cudaGetSymbolAddress((void**)&z,    g_z);

    // 1. pack mask bits
    pack_mask_kernel<<<(Bb * Nn * Nn) / 1024, 1024>>>(adj);
    // 2. reorder W
    transpose_w_kernel<<<(Dd * Dd) / 1024, 1024>>>(W);
    // 3. Wh = h @ Wt   (8192 x 128 x 128)
    sgemm_kernel<<<dim3(Dd / 64, ROWS / 64), 256>>>(h, Wt, nullptr, Wh, ROWS, Dd, Dd, 0);
    // 4. per-(b,h,n) scores + exp tables
    sE_kernel<<<(Bb * Hh * Nn) / 1024, 1024>>>(a);
    // 5. attention
    att_kernel<<<dim3(Nn / 128, Hh, Bb), 128>>>();
    // 6. LN1(hcat + h) -> x
    ln_kernel<<<ROWS, Dd>>>(hcat, h, ln1g, ln1b, x);
    // 7. y = relu(x @ w1 + b1)   (8192 x 256 x 128)
    sgemm_kernel<<<dim3(2 * Dd / 64, ROWS / 64), 256>>>(x, w1, b1, y, ROWS, 2 * Dd, Dd, 1);
    // 8. z = y @ w2 + b2         (8192 x 128 x 256)
    sgemm_kernel<<<dim3(Dd / 64, ROWS / 64), 256>>>(y, w2, b2, z, ROWS, Dd, 2 * Dd, 0);
    // 9. out = LN2(x + z)
    ln_kernel<<<ROWS, Dd>>>(z, x, ln2g, ln2b, out);
}